// round 15
// baseline (speedup 1.0000x reference)
#include <cuda_runtime.h>
#include <cuda_fp16.h>
#include <math.h>
#include <stdint.h>

// Problem constants
#define BB 2
#define TT 2048
#define EE 1024
#define HH 16
#define DH 64
#define FF 4096
#define MM (BB*TT)   // 4096 rows

// Scratch (device globals: no allocation allowed)
__device__ float g_ln [MM*EE];         // as __half
__device__ float g_qkv[MM*3*EE];       // as __half
__device__ float g_att[MM*EE];         // as __half
__device__ float g_x2 [MM*EE];         // fp32
__device__ float g_act[(size_t)MM*FF]; // as __half
__device__ float g_w  [6*1024*1024];   // fp16 weights, NATURAL [K][N] layout

// offsets in halves
#define WH_ATTN 0
#define WH_PROJ (3*EE*EE)
#define WH_MLP1 (WH_PROJ + EE*EE)
#define WH_MLP2 (WH_MLP1 + EE*FF)

// ---------------------------------------------------------------------------
// Helpers
// ---------------------------------------------------------------------------
__device__ __forceinline__ void cp16(uint32_t dst, const void* src) {
    asm volatile("cp.async.cg.shared.global [%0], [%1], 16;\n" :: "r"(dst), "l"(src));
}

__device__ __forceinline__ uint32_t packh2(float a, float b) {
    __half2 h = __floats2half2_rn(a, b);
    return *reinterpret_cast<uint32_t*>(&h);
}

#define MMA_F16(d0,d1,d2,d3,a0,a1,a2,a3,b0,b1) \
    asm volatile( \
        "mma.sync.aligned.m16n8k16.row.col.f32.f16.f16.f32 " \
        "{%0,%1,%2,%3}, {%4,%5,%6,%7}, {%8,%9}, {%0,%1,%2,%3};" \
        : "+f"(d0), "+f"(d1), "+f"(d2), "+f"(d3) \
        : "r"(a0), "r"(a1), "r"(a2), "r"(a3), "r"(b0), "r"(b1))

#define LDSM_X4(r0,r1,r2,r3,addr) \
    asm volatile("ldmatrix.sync.aligned.m8n8.x4.shared.b16 {%0,%1,%2,%3}, [%4];" \
        : "=r"(r0), "=r"(r1), "=r"(r2), "=r"(r3) : "r"(addr))

#define LDSM_X4_T(r0,r1,r2,r3,addr) \
    asm volatile("ldmatrix.sync.aligned.m8n8.x4.trans.shared.b16 {%0,%1,%2,%3}, [%4];" \
        : "=r"(r0), "=r"(r1), "=r"(r2), "=r"(r3) : "r"(addr))

// ---------------------------------------------------------------------------
// Fused prologue: blocks [0,512) do LN1 (warp per row); blocks [512,4608)
// convert all four weight matrices fp32 -> fp16 (grid-stride).
// The two halves are independent; fusing them co-schedules work that the
// stream would otherwise serialize.
// ---------------------------------------------------------------------------
#define CV_S0 786432
#define CV_S1 1048576
#define CV_S2 2097152
#define CV_N  3145728
#define LN_BLOCKS 512
#define PRO_BLOCKS 4608

__global__ void __launch_bounds__(256)
prologue_kernel(const float* __restrict__ x,
                const float* __restrict__ g,
                const float* __restrict__ b,
                __half* __restrict__ lnout,
                const float4* __restrict__ wa,
                const float4* __restrict__ wp,
                const float4* __restrict__ w1,
                const float4* __restrict__ w2,
                uint2* __restrict__ wout) {
    if (blockIdx.x < LN_BLOCKS) {
        // ---- LayerNorm: warp per row ----
        int row  = blockIdx.x * 8 + (threadIdx.x >> 5);
        int lane = threadIdx.x & 31;
        const float4* xr = reinterpret_cast<const float4*>(x + (size_t)row * EE);
        float4 v[8];
        float s = 0.f, sq = 0.f;
        #pragma unroll
        for (int i = 0; i < 8; i++) {
            v[i] = xr[i * 32 + lane];
            s  += v[i].x + v[i].y + v[i].z + v[i].w;
            sq += v[i].x*v[i].x + v[i].y*v[i].y + v[i].z*v[i].z + v[i].w*v[i].w;
        }
        #pragma unroll
        for (int o = 16; o > 0; o >>= 1) {
            s  += __shfl_xor_sync(0xffffffff, s,  o);
            sq += __shfl_xor_sync(0xffffffff, sq, o);
        }
        float mu   = s * (1.0f / EE);
        float rstd = rsqrtf(sq * (1.0f / EE) - mu * mu + 1e-5f);
        uint2* op = reinterpret_cast<uint2*>(lnout + (size_t)row * EE);
        const float4* gr = reinterpret_cast<const float4*>(g);
        const float4* br = reinterpret_cast<const float4*>(b);
        #pragma unroll
        for (int i = 0; i < 8; i++) {
            float4 gv = gr[i * 32 + lane];
            float4 bv = br[i * 32 + lane];
            uint2 o;
            o.x = packh2((v[i].x - mu) * rstd * gv.x + bv.x,
                         (v[i].y - mu) * rstd * gv.y + bv.y);
            o.y = packh2((v[i].z - mu) * rstd * gv.z + bv.z,
                         (v[i].w - mu) * rstd * gv.w + bv.w);
            op[i * 32 + lane] = o;
        }
    } else {
        // ---- Weight convert fp32 -> fp16 (grid-stride over 4096 blocks) ----
        int i = (blockIdx.x - LN_BLOCKS) * blockDim.x + threadIdx.x;
        int stride = (PRO_BLOCKS - LN_BLOCKS) * blockDim.x;
        for (; i < CV_N; i += stride) {
            float4 v;
            if (i < CV_S0)      v = wa[i];
            else if (i < CV_S1) v = wp[i - CV_S0];
            else if (i < CV_S2) v = w1[i - CV_S1];
            else                v = w2[i - CV_S2];
            uint2 o;
            o.x = packh2(v.x, v.y);
            o.y = packh2(v.z, v.w);
            wout[i] = o;
        }
    }
}

// ---------------------------------------------------------------------------
// LayerNorm (standalone, for LN2): warp per row. 8 warps/block.
// ---------------------------------------------------------------------------
__global__ void ln_kernel(const float* __restrict__ x,
                          const float* __restrict__ g,
                          const float* __restrict__ b,
                          __half* __restrict__ out) {
    int row  = blockIdx.x * 8 + (threadIdx.x >> 5);
    int lane = threadIdx.x & 31;
    const float4* xr = reinterpret_cast<const float4*>(x + (size_t)row * EE);
    float4 v[8];
    float s = 0.f, sq = 0.f;
    #pragma unroll
    for (int i = 0; i < 8; i++) {
        v[i] = xr[i * 32 + lane];
        s  += v[i].x + v[i].y + v[i].z + v[i].w;
        sq += v[i].x*v[i].x + v[i].y*v[i].y + v[i].z*v[i].z + v[i].w*v[i].w;
    }
    #pragma unroll
    for (int o = 16; o > 0; o >>= 1) {
        s  += __shfl_xor_sync(0xffffffff, s,  o);
        sq += __shfl_xor_sync(0xffffffff, sq, o);
    }
    float mu   = s * (1.0f / EE);
    float rstd = rsqrtf(sq * (1.0f / EE) - mu * mu + 1e-5f);
    uint2* op = reinterpret_cast<uint2*>(out + (size_t)row * EE);
    const float4* gr = reinterpret_cast<const float4*>(g);
    const float4* br = reinterpret_cast<const float4*>(b);
    #pragma unroll
    for (int i = 0; i < 8; i++) {
        float4 gv = gr[i * 32 + lane];
        float4 bv = br[i * 32 + lane];
        uint2 o;
        o.x = packh2((v[i].x - mu) * rstd * gv.x + bv.x,
                     (v[i].y - mu) * rstd * gv.y + bv.y);
        o.y = packh2((v[i].z - mu) * rstd * gv.z + bv.z,
                     (v[i].w - mu) * rstd * gv.w + bv.w);
        op[i * 32 + lane] = o;
    }
}

__device__ __forceinline__ float gelu_f(float x) {
    const float c = 0.7978845608028654f;
    float x3 = x * x * x;
    return 0.5f * x * (1.0f + tanhf(c * (x + 0.044715f * x3)));
}

// ---------------------------------------------------------------------------
// fp16 GEMM, CTA 128x256x64 (unchanged — at HMMA path rate)
// ---------------------------------------------------------------------------
#define GSTAGE 49152
#define GSMEM_BYTES (3*GSTAGE)

template<bool GELU, bool RES, bool OUTH>
__global__ void __launch_bounds__(256, 1)
mma_gemm(const __half* __restrict__ A, const __half* __restrict__ W,
         const float* __restrict__ bias, const float* __restrict__ res,
         void* __restrict__ Cv, int M, int N, int K) {
    extern __shared__ char smc[];
    const uint32_t sm_u = (uint32_t)__cvta_generic_to_shared(smc);

    const int tid  = threadIdx.x;
    const int lane = tid & 31;
    const int warp = tid >> 5;
    const int wm = warp >> 2;
    const int wn = warp & 3;
    const int g  = lane >> 2;
    const int tg = lane & 3;

    const int bm = blockIdx.y, bn = blockIdx.x;
    const __half* Ab = A + (size_t)bm * 128 * K;
    const __half* Bb = W + (size_t)bn * 256;

    const int j    = lane & 7;
    const int tile = lane >> 3;
    const uint32_t jm = (uint32_t)(j * 16);
    const uint32_t aRowSel = (uint32_t)((tile & 1) * 8);
    const uint32_t aC16    = (uint32_t)((tile >> 1) * 16);
    const uint32_t nbOff   = (uint32_t)((tile >> 1) * 16);

    uint32_t aRow[4];
    #pragma unroll
    for (int mi = 0; mi < 4; mi++)
        aRow[mi] = ((uint32_t)(wm * 64 + mi * 16 + j) + aRowSel) * 128;
    const uint32_t bBase = 16384u + (uint32_t)wn * 128u +
                           (uint32_t)(tile & 1) * 4096u + (uint32_t)j * 512u;

    float acc[4][8][4];
    #pragma unroll
    for (int i = 0; i < 4; i++)
        #pragma unroll
        for (int jj = 0; jj < 8; jj++)
            #pragma unroll
            for (int c = 0; c < 4; c++) acc[i][jj][c] = 0.f;

    auto issue = [&](int stage, int kt) {
        uint32_t sA = sm_u + (uint32_t)stage * GSTAGE;
        uint32_t sB = sA + 16384u;
        {
            int c = tid & 7;
            int kc = kt * 64 + c * 8;
            #pragma unroll
            for (int p = 0; p < 4; p++) {
                int r = (tid >> 3) + p * 32;
                uint32_t dst = (uint32_t)(r * 128) +
                               (((uint32_t)(c * 16)) ^ ((uint32_t)(r & 7) * 16));
                cp16(sA + dst, Ab + (size_t)r * K + kc);
            }
        }
        #pragma unroll
        for (int p = 0; p < 8; p++) {
            int idx = tid + p * 256;
            int r = idx >> 5;
            int c = idx & 31;
            uint32_t dst = (uint32_t)(r * 512) + (uint32_t)((c >> 3) * 128) +
                           (((uint32_t)((c & 7) * 16)) ^ ((uint32_t)(r & 7) * 16));
            cp16(sB + dst, Bb + (size_t)(kt * 64 + r) * N + c * 8);
        }
        asm volatile("cp.async.commit_group;\n");
    };

    const int KT = K >> 6;
    issue(0, 0);
    issue(1, 1);

    int rbuf = 0, ibuf = 2;
    for (int kt = 0; kt < KT; kt++) {
        if (kt + 1 < KT) {
            asm volatile("cp.async.wait_group 1;\n");
        } else {
            asm volatile("cp.async.wait_group 0;\n");
        }
        __syncthreads();
        if (kt + 2 < KT) {
            issue(ibuf, kt + 2);
            if (++ibuf == 3) ibuf = 0;
        }

        const uint32_t stBase = sm_u + (uint32_t)rbuf * GSTAGE;
        if (++rbuf == 3) rbuf = 0;

        #pragma unroll
        for (int ks = 0; ks < 4; ks++) {
            const uint32_t koffA = ((uint32_t)(ks * 32) + aC16) ^ jm;

            uint32_t af[4][4];
            #pragma unroll
            for (int mi = 0; mi < 4; mi++)
                LDSM_X4(af[mi][0], af[mi][1], af[mi][2], af[mi][3],
                        stBase + aRow[mi] + koffA);

            uint32_t bf[8][2];
            const uint32_t bk = stBase + bBase + (uint32_t)ks * 8192u;
            #pragma unroll
            for (int li = 0; li < 4; li++) {
                uint32_t addr = bk + (((uint32_t)(li * 32) + nbOff) ^ jm);
                LDSM_X4_T(bf[li*2][0], bf[li*2][1], bf[li*2+1][0], bf[li*2+1][1], addr);
            }

            #pragma unroll
            for (int mi = 0; mi < 4; mi++)
                #pragma unroll
                for (int ni = 0; ni < 8; ni++)
                    MMA_F16(acc[mi][ni][0], acc[mi][ni][1], acc[mi][ni][2], acc[mi][ni][3],
                            af[mi][0], af[mi][1], af[mi][2], af[mi][3],
                            bf[ni][0], bf[ni][1]);
        }
    }

    const int rowBase = bm * 128 + wm * 64;
    const int colBase = bn * 256 + wn * 64;
    float* Cf = (float*)Cv;
    __half* Ch = (__half*)Cv;
    #pragma unroll
    for (int mi = 0; mi < 4; mi++) {
        #pragma unroll
        for (int ni = 0; ni < 8; ni++) {
            int col = colBase + ni * 8 + 2 * tg;
            float bb0 = bias[col], bb1 = bias[col + 1];
            int r0 = rowBase + mi * 16 + g;
            int r1 = r0 + 8;
            float v0 = acc[mi][ni][0] + bb0;
            float v1 = acc[mi][ni][1] + bb1;
            float v2 = acc[mi][ni][2] + bb0;
            float v3 = acc[mi][ni][3] + bb1;
            if (GELU) { v0 = gelu_f(v0); v1 = gelu_f(v1); v2 = gelu_f(v2); v3 = gelu_f(v3); }
            if (RES) {
                const float2 rr0 = *reinterpret_cast<const float2*>(res + (size_t)r0 * N + col);
                const float2 rr1 = *reinterpret_cast<const float2*>(res + (size_t)r1 * N + col);
                v0 += rr0.x; v1 += rr0.y; v2 += rr1.x; v3 += rr1.y;
            }
            if (OUTH) {
                *reinterpret_cast<__half2*>(Ch + (size_t)r0 * N + col) = __floats2half2_rn(v0, v1);
                *reinterpret_cast<__half2*>(Ch + (size_t)r1 * N + col) = __floats2half2_rn(v2, v3);
            } else {
                *reinterpret_cast<float2*>(Cf + (size_t)r0 * N + col) = make_float2(v0, v1);
                *reinterpret_cast<float2*>(Cf + (size_t)r1 * N + col) = make_float2(v2, v3);
            }
        }
    }
}

// ---------------------------------------------------------------------------
// fp16 flash attention — R12 configuration (best measured):
// 64-query CTAs, 4 warps, register-resident P, 3-stage KV ring,
// one __syncthreads per k-tile, 3 CTAs/SM.
// Smem: K 3x8K @0, V 3x8K @24576, Q 8K @49152 -> 57344 B.
// ---------------------------------------------------------------------------
#define AOFF_V 24576u
#define AOFF_Q 49152u
#define ATT_SMEM 57344

__global__ void __launch_bounds__(128, 3)
attn_mma_kernel(const __half* __restrict__ qkv, __half* __restrict__ out) {
    extern __shared__ char smc[];
    const uint32_t sm_u = (uint32_t)__cvta_generic_to_shared(smc);

    const int qt  = gridDim.x - 1 - blockIdx.x;
    const int qt0 = qt * 64;
    const int h   = blockIdx.y;
    const int b   = blockIdx.z;
    const int tid = threadIdx.x;
    const int lane = tid & 31;
    const int warp = tid >> 5;
    const int g  = lane >> 2;
    const int tg = lane & 3;
    const int r0 = warp * 16 + g;

    const int j    = lane & 7;
    const int tile = lane >> 3;
    const uint32_t jm = (uint32_t)(j * 16);
    const uint32_t aRowSel = (uint32_t)((tile & 1) * 8);
    const uint32_t aC16    = (uint32_t)((tile >> 1) * 16);
    const uint32_t bRowSel = (uint32_t)((tile >> 1) * 8);
    const uint32_t bC16    = (uint32_t)((tile & 1) * 16);

    const __half* base = qkv + (size_t)b * TT * (3 * EE);
    const int sch = (tid & 7) << 4;

    auto issueKV = [&](int stage, int kt) {
        int krow0 = kt * 64;
        uint32_t sK = sm_u + (uint32_t)stage * 8192u;
        uint32_t sV = sm_u + AOFF_V + (uint32_t)stage * 8192u;
        #pragma unroll
        for (int p = 0; p < 4; p++) {
            int r = (tid >> 3) + p * 16;
            uint32_t dst = (uint32_t)(r * 128) + ((uint32_t)sch ^ ((uint32_t)(r & 7) * 16));
            const __half* src = base + (size_t)(krow0 + r) * 3072 + EE + h * 64 + (sch >> 1);
            cp16(sK + dst, src);
            cp16(sV + dst, src + EE);
        }
        asm volatile("cp.async.commit_group;\n");
    };

    const int nkt = qt + 1;
    issueKV(0, 0);
    if (nkt > 1) issueKV(1, 1);

    {
        // Q pre-scale: 1/8 * log2(e) -> softmax in base-2 domain
        const __half2 sc8 = __float2half2_rn(0.18033688f);
        #pragma unroll
        for (int p = 0; p < 4; p++) {
            int r = (tid >> 3) + p * 16;
            uint4 q = *reinterpret_cast<const uint4*>(
                base + (size_t)(qt0 + r) * 3072 + h * 64 + (sch >> 1));
            __half2* qh = reinterpret_cast<__half2*>(&q);
            qh[0] = __hmul2(qh[0], sc8);
            qh[1] = __hmul2(qh[1], sc8);
            qh[2] = __hmul2(qh[2], sc8);
            qh[3] = __hmul2(qh[3], sc8);
            uint32_t dst = AOFF_Q + (uint32_t)(r * 128) +
                           ((uint32_t)sch ^ ((uint32_t)(r & 7) * 16));
            *reinterpret_cast<uint4*>(smc + dst) = q;
        }
    }
    __syncthreads();

    uint32_t qa[4][4];
    #pragma unroll
    for (int ks = 0; ks < 4; ks++) {
        uint32_t addr = sm_u + AOFF_Q +
            ((uint32_t)(warp * 16 + j) + aRowSel) * 128 +
            (((uint32_t)(ks * 32) + aC16) ^ jm);
        LDSM_X4(qa[ks][0], qa[ks][1], qa[ks][2], qa[ks][3], addr);
    }

    float m0 = -1e30f, m1 = -1e30f, l0 = 0.f, l1 = 0.f;
    float ob[8][4];
    #pragma unroll
    for (int nt = 0; nt < 8; nt++)
        #pragma unroll
        for (int c = 0; c < 4; c++) ob[nt][c] = 0.f;

    int rstage = 0, istage = 2;
    for (int kt = 0; kt < nkt; kt++) {
        if (kt + 1 < nkt) {
            asm volatile("cp.async.wait_group 1;\n");
        } else {
            asm volatile("cp.async.wait_group 0;\n");
        }
        __syncthreads();
        if (kt + 2 < nkt) {
            issueKV(istage, kt + 2);
            if (++istage == 3) istage = 0;
        }

        const uint32_t sK = sm_u + (uint32_t)rstage * 8192u;
        const uint32_t sV = sm_u + AOFF_V + (uint32_t)rstage * 8192u;
        if (++rstage == 3) rstage = 0;

        // S = Q @ K^T
        float sc[8][4];
        #pragma unroll
        for (int nt = 0; nt < 8; nt++)
            #pragma unroll
            for (int c = 0; c < 4; c++) sc[nt][c] = 0.f;

        #pragma unroll
        for (int ks = 0; ks < 4; ks++) {
            const uint32_t koffB = ((uint32_t)(ks * 32) + bC16) ^ jm;
            uint32_t bfr[8][2];
            #pragma unroll
            for (int bi = 0; bi < 4; bi++) {
                uint32_t addr = sK + ((uint32_t)(bi * 16 + j) + bRowSel) * 128 + koffB;
                LDSM_X4(bfr[bi*2][0], bfr[bi*2][1], bfr[bi*2+1][0], bfr[bi*2+1][1], addr);
            }
            #pragma unroll
            for (int nt = 0; nt < 8; nt++)
                MMA_F16(sc[nt][0], sc[nt][1], sc[nt][2], sc[nt][3],
                        qa[ks][0], qa[ks][1], qa[ks][2], qa[ks][3],
                        bfr[nt][0], bfr[nt][1]);
        }

        // Causal mask (diagonal tile)
        if (kt == nkt - 1) {
            int qrow0 = qt0 + r0;
            int qrow1 = qrow0 + 8;
            #pragma unroll
            for (int nt = 0; nt < 8; nt++) {
                int kc0 = kt * 64 + nt * 8 + 2 * tg;
                if (kc0     > qrow0) sc[nt][0] = -1e30f;
                if (kc0 + 1 > qrow0) sc[nt][1] = -1e30f;
                if (kc0     > qrow1) sc[nt][2] = -1e30f;
                if (kc0 + 1 > qrow1) sc[nt][3] = -1e30f;
            }
        }

        // Online softmax (base-2)
        float rm0 = -1e30f, rm1 = -1e30f;
        #pragma unroll
        for (int nt = 0; nt < 8; nt++) {
            rm0 = fmaxf(rm0, fmaxf(sc[nt][0], sc[nt][1]));
            rm1 = fmaxf(rm1, fmaxf(sc[nt][2], sc[nt][3]));
        }
        rm0 = fmaxf(rm0, __shfl_xor_sync(0xffffffff, rm0, 1));
        rm0 = fmaxf(rm0, __shfl_xor_sync(0xffffffff, rm0, 2));
        rm1 = fmaxf(rm1, __shfl_xor_sync(0xffffffff, rm1, 1));
        rm1 = fmaxf(rm1, __shfl_xor_sync(0xffffffff, rm1, 2));
        float mn0 = fmaxf(m0, rm0);
        float mn1 = fmaxf(m1, rm1);

        float rs0 = 0.f, rs1 = 0.f;
        #pragma unroll
        for (int nt = 0; nt < 8; nt++) {
            sc[nt][0] = exp2f(sc[nt][0] - mn0);
            sc[nt][1] = exp2f(sc[nt][1] - mn0);
            sc[nt][2] = exp2f(sc[nt][2] - mn1);
            sc[nt][3] = exp2f(sc[nt][3] - mn1);
            rs0 += sc[nt][0] + sc[nt][1];
            rs1 += sc[nt][2] + sc[nt][3];
        }
        rs0 += __shfl_xor_sync(0xffffffff, rs0, 1);
        rs0 += __shfl_xor_sync(0xffffffff, rs0, 2);
        rs1 += __shfl_xor_sync(0xffffffff, rs1, 1);
        rs1 += __shfl_xor_sync(0xffffffff, rs1, 2);

        float scale0 = exp2f(m0 - mn0);
        float scale1 = exp2f(m1 - mn1);
        l0 = l0 * scale0 + rs0;
        l1 = l1 * scale1 + rs1;
        m0 = mn0; m1 = mn1;
        #pragma unroll
        for (int nt = 0; nt < 8; nt++) {
            ob[nt][0] *= scale0; ob[nt][1] *= scale0;
            ob[nt][2] *= scale1; ob[nt][3] *= scale1;
        }

        // O += P @ V — P fragments packed directly from sc registers
        #pragma unroll
        for (int ks = 0; ks < 4; ks++) {
            uint32_t pa0 = packh2(sc[2*ks][0],   sc[2*ks][1]);
            uint32_t pa1 = packh2(sc[2*ks][2],   sc[2*ks][3]);
            uint32_t pa2 = packh2(sc[2*ks+1][0], sc[2*ks+1][1]);
            uint32_t pa3 = packh2(sc[2*ks+1][2], sc[2*ks+1][3]);
            uint32_t vf[8][2];
            #pragma unroll
            for (int li = 0; li < 4; li++) {
                uint32_t addr = sV +
                    (uint32_t)((ks * 16 + (tile & 1) * 8 + j) * 128) +
                    (((uint32_t)(li * 32 + (tile >> 1) * 16)) ^ jm);
                LDSM_X4_T(vf[li*2][0], vf[li*2][1], vf[li*2+1][0], vf[li*2+1][1], addr);
            }
            #pragma unroll
            for (int nt = 0; nt < 8; nt++)
                MMA_F16(ob[nt][0], ob[nt][1], ob[nt][2], ob[nt][3],
                        pa0, pa1, pa2, pa3, vf[nt][0], vf[nt][1]);
        }
    }

    float inv0 = 1.0f / l0;
    float inv1 = 1.0f / l1;
    size_t row0 = ((size_t)b * TT + qt0 + r0) * EE + h * 64;
    size_t row1 = row0 + 8 * EE;
    #pragma unroll
    for (int nt = 0; nt < 8; nt++) {
        int col = nt * 8 + 2 * tg;
        *reinterpret_cast<__half2*>(out + row0 + col) =
            __floats2half2_rn(ob[nt][0] * inv0, ob[nt][1] * inv0);
        *reinterpret_cast<__half2*>(out + row1 + col) =
            __floats2half2_rn(ob[nt][2] * inv1, ob[nt][3] * inv1);
    }
}

// ---------------------------------------------------------------------------
// Launch
// ---------------------------------------------------------------------------
extern "C" void kernel_launch(void* const* d_in, const int* in_sizes, int n_in,
                              void* d_out, int out_size) {
    const float* x        = (const float*)d_in[0];
    const float* c_attn_w = (const float*)d_in[1];
    const float* c_attn_b = (const float*)d_in[2];
    const float* c_proj_w = (const float*)d_in[3];
    const float* c_proj_b = (const float*)d_in[4];
    const float* mlp_w1   = (const float*)d_in[5];
    const float* mlp_b1   = (const float*)d_in[6];
    const float* mlp_w2   = (const float*)d_in[7];
    const float* mlp_b2   = (const float*)d_in[8];
    const float* ln1_g    = (const float*)d_in[9];
    const float* ln1_b    = (const float*)d_in[10];
    const float* ln2_g    = (const float*)d_in[11];
    const float* ln2_b    = (const float*)d_in[12];
    float* out = (float*)d_out;

    float *lnf, *qkvf, *attf, *x2, *actf, *wf;
    cudaGetSymbolAddress((void**)&lnf,  g_ln);
    cudaGetSymbolAddress((void**)&qkvf, g_qkv);
    cudaGetSymbolAddress((void**)&attf, g_att);
    cudaGetSymbolAddress((void**)&x2,   g_x2);
    cudaGetSymbolAddress((void**)&actf, g_act);
    cudaGetSymbolAddress((void**)&wf,   g_w);
    __half* ln  = (__half*)lnf;
    __half* qkv = (__half*)qkvf;
    __half* att = (__half*)attf;
    __half* act = (__half*)actf;
    __half* w   = (__half*)wf;

    cudaFuncSetAttribute(mma_gemm<false, false, true>,
                         cudaFuncAttributeMaxDynamicSharedMemorySize, GSMEM_BYTES);
    cudaFuncSetAttribute(mma_gemm<false, true, false>,
                         cudaFuncAttributeMaxDynamicSharedMemorySize, GSMEM_BYTES);
    cudaFuncSetAttribute(mma_gemm<true, false, true>,
                         cudaFuncAttributeMaxDynamicSharedMemorySize, GSMEM_BYTES);
    cudaFuncSetAttribute(attn_mma_kernel,
                         cudaFuncAttributeMaxDynamicSharedMemorySize, ATT_SMEM);

    // 0. Fused prologue: LN1 (blocks 0..511) || weight convert (blocks 512..4607)
    prologue_kernel<<<PRO_BLOCKS, 256>>>(
        x, ln1_g, ln1_b, ln,
        (const float4*)c_attn_w, (const float4*)c_proj_w,
        (const float4*)mlp_w1, (const float4*)mlp_w2,
        (uint2*)w);

    // 1. QKV = ln @ c_attn_w + b           [4096, 3072] fp16 out
    mma_gemm<false, false, true><<<dim3(3*EE/256, MM/128), 256, GSMEM_BYTES>>>(
        ln, w + WH_ATTN, c_attn_b, nullptr, qkv, MM, 3*EE, EE);
    // 2. Attention (64-query CTAs, register-resident P, 3-stage KV)
    attn_mma_kernel<<<dim3(TT/64, HH, BB), 128, ATT_SMEM>>>(qkv, att);
    // 3. x2 = x + att @ c_proj_w + b       [4096, 1024] fp32 out
    mma_gemm<false, true, false><<<dim3(EE/256, MM/128), 256, GSMEM_BYTES>>>(
        att, w + WH_PROJ, c_proj_b, x, x2, MM, EE, EE);
    // 4. LN2 (fp16 out)
    ln_kernel<<<MM/8, 256>>>(x2, ln2_g, ln2_b, ln);
    // 5. act = gelu(h @ mlp_w1 + b1)       [4096, 4096] fp16 out
    mma_gemm<true, false, true><<<dim3(FF/256, MM/128), 256, GSMEM_BYTES>>>(
        ln, w + WH_MLP1, mlp_b1, nullptr, act, MM, FF, EE);
    // 6. out = x2 + act @ mlp_w2 + b2      [4096, 1024] fp32 out
    mma_gemm<false, true, false><<<dim3(EE/256, MM/128), 256, GSMEM_BYTES>>>(
        act, w + WH_MLP2, mlp_b2, x2, out, MM, EE, FF);
}

// round 16
// speedup vs baseline: 1.0046x; 1.0046x over previous
#include <cuda_runtime.h>
#include <cuda_fp16.h>
#include <math.h>
#include <stdint.h>

// Problem constants
#define BB 2
#define TT 2048
#define EE 1024
#define HH 16
#define DH 64
#define FF 4096
#define MM (BB*TT)   // 4096 rows

// Scratch (device globals: no allocation allowed)
__device__ float g_ln [MM*EE];         // as __half
__device__ float g_qkv[MM*3*EE];       // as __half
__device__ float g_att[MM*EE];         // as __half
__device__ float g_x2 [MM*EE];         // fp32
__device__ float g_act[(size_t)MM*FF]; // as __half
__device__ float g_w  [6*1024*1024];   // fp16 weights, NATURAL [K][N] layout

// offsets in halves
#define WH_ATTN 0
#define WH_PROJ (3*EE*EE)
#define WH_MLP1 (WH_PROJ + EE*EE)
#define WH_MLP2 (WH_MLP1 + EE*FF)

// ---------------------------------------------------------------------------
// Helpers
// ---------------------------------------------------------------------------
__device__ __forceinline__ void cp16(uint32_t dst, const void* src) {
    asm volatile("cp.async.cg.shared.global [%0], [%1], 16;\n" :: "r"(dst), "l"(src));
}

__device__ __forceinline__ uint32_t packh2(float a, float b) {
    __half2 h = __floats2half2_rn(a, b);
    return *reinterpret_cast<uint32_t*>(&h);
}

#define MMA_F16(d0,d1,d2,d3,a0,a1,a2,a3,b0,b1) \
    asm volatile( \
        "mma.sync.aligned.m16n8k16.row.col.f32.f16.f16.f32 " \
        "{%0,%1,%2,%3}, {%4,%5,%6,%7}, {%8,%9}, {%0,%1,%2,%3};" \
        : "+f"(d0), "+f"(d1), "+f"(d2), "+f"(d3) \
        : "r"(a0), "r"(a1), "r"(a2), "r"(a3), "r"(b0), "r"(b1))

#define LDSM_X4(r0,r1,r2,r3,addr) \
    asm volatile("ldmatrix.sync.aligned.m8n8.x4.shared.b16 {%0,%1,%2,%3}, [%4];" \
        : "=r"(r0), "=r"(r1), "=r"(r2), "=r"(r3) : "r"(addr))

#define LDSM_X4_T(r0,r1,r2,r3,addr) \
    asm volatile("ldmatrix.sync.aligned.m8n8.x4.trans.shared.b16 {%0,%1,%2,%3}, [%4];" \
        : "=r"(r0), "=r"(r1), "=r"(r2), "=r"(r3) : "r"(addr))

// ---------------------------------------------------------------------------
// Fused fp32->fp16 convert for all four weights (dsts contiguous in g_w)
// ---------------------------------------------------------------------------
#define CV_S0 786432
#define CV_S1 1048576
#define CV_S2 2097152
#define CV_N  3145728
__global__ void convert_all_kernel(const float4* __restrict__ wa,
                                   const float4* __restrict__ wp,
                                   const float4* __restrict__ w1,
                                   const float4* __restrict__ w2,
                                   uint2* __restrict__ out) {
    int i = blockIdx.x * blockDim.x + threadIdx.x;
    int stride = gridDim.x * blockDim.x;
    for (; i < CV_N; i += stride) {
        float4 v;
        if (i < CV_S0)      v = wa[i];
        else if (i < CV_S1) v = wp[i - CV_S0];
        else if (i < CV_S2) v = w1[i - CV_S1];
        else                v = w2[i - CV_S2];
        uint2 o;
        o.x = packh2(v.x, v.y);
        o.y = packh2(v.z, v.w);
        out[i] = o;
    }
}

// ---------------------------------------------------------------------------
// LayerNorm: warp per row. 8 warps/block.
// ---------------------------------------------------------------------------
__global__ void ln_kernel(const float* __restrict__ x,
                          const float* __restrict__ g,
                          const float* __restrict__ b,
                          __half* __restrict__ out) {
    int row  = blockIdx.x * 8 + (threadIdx.x >> 5);
    int lane = threadIdx.x & 31;
    const float4* xr = reinterpret_cast<const float4*>(x + (size_t)row * EE);
    float4 v[8];
    float s = 0.f, sq = 0.f;
    #pragma unroll
    for (int i = 0; i < 8; i++) {
        v[i] = xr[i * 32 + lane];
        s  += v[i].x + v[i].y + v[i].z + v[i].w;
        sq += v[i].x*v[i].x + v[i].y*v[i].y + v[i].z*v[i].z + v[i].w*v[i].w;
    }
    #pragma unroll
    for (int o = 16; o > 0; o >>= 1) {
        s  += __shfl_xor_sync(0xffffffff, s,  o);
        sq += __shfl_xor_sync(0xffffffff, sq, o);
    }
    float mu   = s * (1.0f / EE);
    float rstd = rsqrtf(sq * (1.0f / EE) - mu * mu + 1e-5f);
    uint2* op = reinterpret_cast<uint2*>(out + (size_t)row * EE);
    const float4* gr = reinterpret_cast<const float4*>(g);
    const float4* br = reinterpret_cast<const float4*>(b);
    #pragma unroll
    for (int i = 0; i < 8; i++) {
        float4 gv = gr[i * 32 + lane];
        float4 bv = br[i * 32 + lane];
        uint2 o;
        o.x = packh2((v[i].x - mu) * rstd * gv.x + bv.x,
                     (v[i].y - mu) * rstd * gv.y + bv.y);
        o.y = packh2((v[i].z - mu) * rstd * gv.z + bv.z,
                     (v[i].w - mu) * rstd * gv.w + bv.w);
        op[i * 32 + lane] = o;
    }
}

__device__ __forceinline__ float gelu_f(float x) {
    const float c = 0.7978845608028654f;
    float x3 = x * x * x;
    return 0.5f * x * (1.0f + tanhf(c * (x + 0.044715f * x3)));
}

// ---------------------------------------------------------------------------
// fp16 GEMM, CTA 128x256x64, 8 warps (2x4), warp tile 64x64, fp32 accum.
// (R12 mainloop; epilogue bias loads vectorized to float2)
// ---------------------------------------------------------------------------
#define GSTAGE 49152
#define GSMEM_BYTES (3*GSTAGE)

template<bool GELU, bool RES, bool OUTH>
__global__ void __launch_bounds__(256, 1)
mma_gemm(const __half* __restrict__ A, const __half* __restrict__ W,
         const float* __restrict__ bias, const float* __restrict__ res,
         void* __restrict__ Cv, int M, int N, int K) {
    extern __shared__ char smc[];
    const uint32_t sm_u = (uint32_t)__cvta_generic_to_shared(smc);

    const int tid  = threadIdx.x;
    const int lane = tid & 31;
    const int warp = tid >> 5;
    const int wm = warp >> 2;
    const int wn = warp & 3;
    const int g  = lane >> 2;
    const int tg = lane & 3;

    const int bm = blockIdx.y, bn = blockIdx.x;
    const __half* Ab = A + (size_t)bm * 128 * K;
    const __half* Bb = W + (size_t)bn * 256;

    const int j    = lane & 7;
    const int tile = lane >> 3;
    const uint32_t jm = (uint32_t)(j * 16);
    const uint32_t aRowSel = (uint32_t)((tile & 1) * 8);
    const uint32_t aC16    = (uint32_t)((tile >> 1) * 16);
    const uint32_t nbOff   = (uint32_t)((tile >> 1) * 16);

    uint32_t aRow[4];
    #pragma unroll
    for (int mi = 0; mi < 4; mi++)
        aRow[mi] = ((uint32_t)(wm * 64 + mi * 16 + j) + aRowSel) * 128;
    const uint32_t bBase = 16384u + (uint32_t)wn * 128u +
                           (uint32_t)(tile & 1) * 4096u + (uint32_t)j * 512u;

    float acc[4][8][4];
    #pragma unroll
    for (int i = 0; i < 4; i++)
        #pragma unroll
        for (int jj = 0; jj < 8; jj++)
            #pragma unroll
            for (int c = 0; c < 4; c++) acc[i][jj][c] = 0.f;

    auto issue = [&](int stage, int kt) {
        uint32_t sA = sm_u + (uint32_t)stage * GSTAGE;
        uint32_t sB = sA + 16384u;
        {
            int c = tid & 7;
            int kc = kt * 64 + c * 8;
            #pragma unroll
            for (int p = 0; p < 4; p++) {
                int r = (tid >> 3) + p * 32;
                uint32_t dst = (uint32_t)(r * 128) +
                               (((uint32_t)(c * 16)) ^ ((uint32_t)(r & 7) * 16));
                cp16(sA + dst, Ab + (size_t)r * K + kc);
            }
        }
        #pragma unroll
        for (int p = 0; p < 8; p++) {
            int idx = tid + p * 256;
            int r = idx >> 5;
            int c = idx & 31;
            uint32_t dst = (uint32_t)(r * 512) + (uint32_t)((c >> 3) * 128) +
                           (((uint32_t)((c & 7) * 16)) ^ ((uint32_t)(r & 7) * 16));
            cp16(sB + dst, Bb + (size_t)(kt * 64 + r) * N + c * 8);
        }
        asm volatile("cp.async.commit_group;\n");
    };

    const int KT = K >> 6;
    issue(0, 0);
    issue(1, 1);

    int rbuf = 0, ibuf = 2;
    for (int kt = 0; kt < KT; kt++) {
        if (kt + 1 < KT) {
            asm volatile("cp.async.wait_group 1;\n");
        } else {
            asm volatile("cp.async.wait_group 0;\n");
        }
        __syncthreads();
        if (kt + 2 < KT) {
            issue(ibuf, kt + 2);
            if (++ibuf == 3) ibuf = 0;
        }

        const uint32_t stBase = sm_u + (uint32_t)rbuf * GSTAGE;
        if (++rbuf == 3) rbuf = 0;

        #pragma unroll
        for (int ks = 0; ks < 4; ks++) {
            const uint32_t koffA = ((uint32_t)(ks * 32) + aC16) ^ jm;

            uint32_t af[4][4];
            #pragma unroll
            for (int mi = 0; mi < 4; mi++)
                LDSM_X4(af[mi][0], af[mi][1], af[mi][2], af[mi][3],
                        stBase + aRow[mi] + koffA);

            uint32_t bf[8][2];
            const uint32_t bk = stBase + bBase + (uint32_t)ks * 8192u;
            #pragma unroll
            for (int li = 0; li < 4; li++) {
                uint32_t addr = bk + (((uint32_t)(li * 32) + nbOff) ^ jm);
                LDSM_X4_T(bf[li*2][0], bf[li*2][1], bf[li*2+1][0], bf[li*2+1][1], addr);
            }

            #pragma unroll
            for (int mi = 0; mi < 4; mi++)
                #pragma unroll
                for (int ni = 0; ni < 8; ni++)
                    MMA_F16(acc[mi][ni][0], acc[mi][ni][1], acc[mi][ni][2], acc[mi][ni][3],
                            af[mi][0], af[mi][1], af[mi][2], af[mi][3],
                            bf[ni][0], bf[ni][1]);
        }
    }

    const int rowBase = bm * 128 + wm * 64;
    const int colBase = bn * 256 + wn * 64;
    float* Cf = (float*)Cv;
    __half* Ch = (__half*)Cv;
    // Vectorized bias loads (col = colBase + ni*8 + 2*tg is 8B-aligned)
    float2 bb[8];
    #pragma unroll
    for (int ni = 0; ni < 8; ni++)
        bb[ni] = *reinterpret_cast<const float2*>(bias + colBase + ni * 8 + 2 * tg);
    #pragma unroll
    for (int mi = 0; mi < 4; mi++) {
        #pragma unroll
        for (int ni = 0; ni < 8; ni++) {
            int col = colBase + ni * 8 + 2 * tg;
            int r0 = rowBase + mi * 16 + g;
            int r1 = r0 + 8;
            float v0 = acc[mi][ni][0] + bb[ni].x;
            float v1 = acc[mi][ni][1] + bb[ni].y;
            float v2 = acc[mi][ni][2] + bb[ni].x;
            float v3 = acc[mi][ni][3] + bb[ni].y;
            if (GELU) { v0 = gelu_f(v0); v1 = gelu_f(v1); v2 = gelu_f(v2); v3 = gelu_f(v3); }
            if (RES) {
                const float2 rr0 = *reinterpret_cast<const float2*>(res + (size_t)r0 * N + col);
                const float2 rr1 = *reinterpret_cast<const float2*>(res + (size_t)r1 * N + col);
                v0 += rr0.x; v1 += rr0.y; v2 += rr1.x; v3 += rr1.y;
            }
            if (OUTH) {
                *reinterpret_cast<__half2*>(Ch + (size_t)r0 * N + col) = __floats2half2_rn(v0, v1);
                *reinterpret_cast<__half2*>(Ch + (size_t)r1 * N + col) = __floats2half2_rn(v2, v3);
            } else {
                *reinterpret_cast<float2*>(Cf + (size_t)r0 * N + col) = make_float2(v0, v1);
                *reinterpret_cast<float2*>(Cf + (size_t)r1 * N + col) = make_float2(v2, v3);
            }
        }
    }
}

// ---------------------------------------------------------------------------
// fp16 flash attention — R12 configuration (best measured):
// 64-query CTAs, 4 warps, register-resident P, 3-stage KV ring,
// one __syncthreads per k-tile, 3 CTAs/SM.
// Smem: K 3x8K @0, V 3x8K @24576, Q 8K @49152 -> 57344 B.
// ---------------------------------------------------------------------------
#define AOFF_V 24576u
#define AOFF_Q 49152u
#define ATT_SMEM 57344

__global__ void __launch_bounds__(128, 3)
attn_mma_kernel(const __half* __restrict__ qkv, __half* __restrict__ out) {
    extern __shared__ char smc[];
    const uint32_t sm_u = (uint32_t)__cvta_generic_to_shared(smc);

    const int qt  = gridDim.x - 1 - blockIdx.x;
    const int qt0 = qt * 64;
    const int h   = blockIdx.y;
    const int b   = blockIdx.z;
    const int tid = threadIdx.x;
    const int lane = tid & 31;
    const int warp = tid >> 5;
    const int g  = lane >> 2;
    const int tg = lane & 3;
    const int r0 = warp * 16 + g;

    const int j    = lane & 7;
    const int tile = lane >> 3;
    const uint32_t jm = (uint32_t)(j * 16);
    const uint32_t aRowSel = (uint32_t)((tile & 1) * 8);
    const uint32_t aC16    = (uint32_t)((tile >> 1) * 16);
    const uint32_t bRowSel = (uint32_t)((tile >> 1) * 8);
    const uint32_t bC16    = (uint32_t)((tile & 1) * 16);

    const __half* base = qkv + (size_t)b * TT * (3 * EE);
    const int sch = (tid & 7) << 4;

    auto issueKV = [&](int stage, int kt) {
        int krow0 = kt * 64;
        uint32_t sK = sm_u + (uint32_t)stage * 8192u;
        uint32_t sV = sm_u + AOFF_V + (uint32_t)stage * 8192u;
        #pragma unroll
        for (int p = 0; p < 4; p++) {
            int r = (tid >> 3) + p * 16;
            uint32_t dst = (uint32_t)(r * 128) + ((uint32_t)sch ^ ((uint32_t)(r & 7) * 16));
            const __half* src = base + (size_t)(krow0 + r) * 3072 + EE + h * 64 + (sch >> 1);
            cp16(sK + dst, src);
            cp16(sV + dst, src + EE);
        }
        asm volatile("cp.async.commit_group;\n");
    };

    const int nkt = qt + 1;
    issueKV(0, 0);
    if (nkt > 1) issueKV(1, 1);

    {
        // Q pre-scale: 1/8 * log2(e) -> softmax in base-2 domain
        const __half2 sc8 = __float2half2_rn(0.18033688f);
        #pragma unroll
        for (int p = 0; p < 4; p++) {
            int r = (tid >> 3) + p * 16;
            uint4 q = *reinterpret_cast<const uint4*>(
                base + (size_t)(qt0 + r) * 3072 + h * 64 + (sch >> 1));
            __half2* qh = reinterpret_cast<__half2*>(&q);
            qh[0] = __hmul2(qh[0], sc8);
            qh[1] = __hmul2(qh[1], sc8);
            qh[2] = __hmul2(qh[2], sc8);
            qh[3] = __hmul2(qh[3], sc8);
            uint32_t dst = AOFF_Q + (uint32_t)(r * 128) +
                           ((uint32_t)sch ^ ((uint32_t)(r & 7) * 16));
            *reinterpret_cast<uint4*>(smc + dst) = q;
        }
    }
    __syncthreads();

    uint32_t qa[4][4];
    #pragma unroll
    for (int ks = 0; ks < 4; ks++) {
        uint32_t addr = sm_u + AOFF_Q +
            ((uint32_t)(warp * 16 + j) + aRowSel) * 128 +
            (((uint32_t)(ks * 32) + aC16) ^ jm);
        LDSM_X4(qa[ks][0], qa[ks][1], qa[ks][2], qa[ks][3], addr);
    }

    float m0 = -1e30f, m1 = -1e30f, l0 = 0.f, l1 = 0.f;
    float ob[8][4];
    #pragma unroll
    for (int nt = 0; nt < 8; nt++)
        #pragma unroll
        for (int c = 0; c < 4; c++) ob[nt][c] = 0.f;

    int rstage = 0, istage = 2;
    for (int kt = 0; kt < nkt; kt++) {
        if (kt + 1 < nkt) {
            asm volatile("cp.async.wait_group 1;\n");
        } else {
            asm volatile("cp.async.wait_group 0;\n");
        }
        __syncthreads();
        if (kt + 2 < nkt) {
            issueKV(istage, kt + 2);
            if (++istage == 3) istage = 0;
        }

        const uint32_t sK = sm_u + (uint32_t)rstage * 8192u;
        const uint32_t sV = sm_u + AOFF_V + (uint32_t)rstage * 8192u;
        if (++rstage == 3) rstage = 0;

        // S = Q @ K^T
        float sc[8][4];
        #pragma unroll
        for (int nt = 0; nt < 8; nt++)
            #pragma unroll
            for (int c = 0; c < 4; c++) sc[nt][c] = 0.f;

        #pragma unroll
        for (int ks = 0; ks < 4; ks++) {
            const uint32_t koffB = ((uint32_t)(ks * 32) + bC16) ^ jm;
            uint32_t bfr[8][2];
            #pragma unroll
            for (int bi = 0; bi < 4; bi++) {
                uint32_t addr = sK + ((uint32_t)(bi * 16 + j) + bRowSel) * 128 + koffB;
                LDSM_X4(bfr[bi*2][0], bfr[bi*2][1], bfr[bi*2+1][0], bfr[bi*2+1][1], addr);
            }
            #pragma unroll
            for (int nt = 0; nt < 8; nt++)
                MMA_F16(sc[nt][0], sc[nt][1], sc[nt][2], sc[nt][3],
                        qa[ks][0], qa[ks][1], qa[ks][2], qa[ks][3],
                        bfr[nt][0], bfr[nt][1]);
        }

        // Causal mask (diagonal tile)
        if (kt == nkt - 1) {
            int qrow0 = qt0 + r0;
            int qrow1 = qrow0 + 8;
            #pragma unroll
            for (int nt = 0; nt < 8; nt++) {
                int kc0 = kt * 64 + nt * 8 + 2 * tg;
                if (kc0     > qrow0) sc[nt][0] = -1e30f;
                if (kc0 + 1 > qrow0) sc[nt][1] = -1e30f;
                if (kc0     > qrow1) sc[nt][2] = -1e30f;
                if (kc0 + 1 > qrow1) sc[nt][3] = -1e30f;
            }
        }

        // Online softmax (base-2)
        float rm0 = -1e30f, rm1 = -1e30f;
        #pragma unroll
        for (int nt = 0; nt < 8; nt++) {
            rm0 = fmaxf(rm0, fmaxf(sc[nt][0], sc[nt][1]));
            rm1 = fmaxf(rm1, fmaxf(sc[nt][2], sc[nt][3]));
        }
        rm0 = fmaxf(rm0, __shfl_xor_sync(0xffffffff, rm0, 1));
        rm0 = fmaxf(rm0, __shfl_xor_sync(0xffffffff, rm0, 2));
        rm1 = fmaxf(rm1, __shfl_xor_sync(0xffffffff, rm1, 1));
        rm1 = fmaxf(rm1, __shfl_xor_sync(0xffffffff, rm1, 2));
        float mn0 = fmaxf(m0, rm0);
        float mn1 = fmaxf(m1, rm1);

        float rs0 = 0.f, rs1 = 0.f;
        #pragma unroll
        for (int nt = 0; nt < 8; nt++) {
            sc[nt][0] = exp2f(sc[nt][0] - mn0);
            sc[nt][1] = exp2f(sc[nt][1] - mn0);
            sc[nt][2] = exp2f(sc[nt][2] - mn1);
            sc[nt][3] = exp2f(sc[nt][3] - mn1);
            rs0 += sc[nt][0] + sc[nt][1];
            rs1 += sc[nt][2] + sc[nt][3];
        }
        rs0 += __shfl_xor_sync(0xffffffff, rs0, 1);
        rs0 += __shfl_xor_sync(0xffffffff, rs0, 2);
        rs1 += __shfl_xor_sync(0xffffffff, rs1, 1);
        rs1 += __shfl_xor_sync(0xffffffff, rs1, 2);

        float scale0 = exp2f(m0 - mn0);
        float scale1 = exp2f(m1 - mn1);
        l0 = l0 * scale0 + rs0;
        l1 = l1 * scale1 + rs1;
        m0 = mn0; m1 = mn1;
        #pragma unroll
        for (int nt = 0; nt < 8; nt++) {
            ob[nt][0] *= scale0; ob[nt][1] *= scale0;
            ob[nt][2] *= scale1; ob[nt][3] *= scale1;
        }

        // O += P @ V — P fragments packed directly from sc registers
        #pragma unroll
        for (int ks = 0; ks < 4; ks++) {
            uint32_t pa0 = packh2(sc[2*ks][0],   sc[2*ks][1]);
            uint32_t pa1 = packh2(sc[2*ks][2],   sc[2*ks][3]);
            uint32_t pa2 = packh2(sc[2*ks+1][0], sc[2*ks+1][1]);
            uint32_t pa3 = packh2(sc[2*ks+1][2], sc[2*ks+1][3]);
            uint32_t vf[8][2];
            #pragma unroll
            for (int li = 0; li < 4; li++) {
                uint32_t addr = sV +
                    (uint32_t)((ks * 16 + (tile & 1) * 8 + j) * 128) +
                    (((uint32_t)(li * 32 + (tile >> 1) * 16)) ^ jm);
                LDSM_X4_T(vf[li*2][0], vf[li*2][1], vf[li*2+1][0], vf[li*2+1][1], addr);
            }
            #pragma unroll
            for (int nt = 0; nt < 8; nt++)
                MMA_F16(ob[nt][0], ob[nt][1], ob[nt][2], ob[nt][3],
                        pa0, pa1, pa2, pa3, vf[nt][0], vf[nt][1]);
        }
    }

    float inv0 = 1.0f / l0;
    float inv1 = 1.0f / l1;
    size_t row0 = ((size_t)b * TT + qt0 + r0) * EE + h * 64;
    size_t row1 = row0 + 8 * EE;
    #pragma unroll
    for (int nt = 0; nt < 8; nt++) {
        int col = nt * 8 + 2 * tg;
        *reinterpret_cast<__half2*>(out + row0 + col) =
            __floats2half2_rn(ob[nt][0] * inv0, ob[nt][1] * inv0);
        *reinterpret_cast<__half2*>(out + row1 + col) =
            __floats2half2_rn(ob[nt][2] * inv1, ob[nt][3] * inv1);
    }
}

// ---------------------------------------------------------------------------
// Launch
// ---------------------------------------------------------------------------
extern "C" void kernel_launch(void* const* d_in, const int* in_sizes, int n_in,
                              void* d_out, int out_size) {
    const float* x        = (const float*)d_in[0];
    const float* c_attn_w = (const float*)d_in[1];
    const float* c_attn_b = (const float*)d_in[2];
    const float* c_proj_w = (const float*)d_in[3];
    const float* c_proj_b = (const float*)d_in[4];
    const float* mlp_w1   = (const float*)d_in[5];
    const float* mlp_b1   = (const float*)d_in[6];
    const float* mlp_w2   = (const float*)d_in[7];
    const float* mlp_b2   = (const float*)d_in[8];
    const float* ln1_g    = (const float*)d_in[9];
    const float* ln1_b    = (const float*)d_in[10];
    const float* ln2_g    = (const float*)d_in[11];
    const float* ln2_b    = (const float*)d_in[12];
    float* out = (float*)d_out;

    float *lnf, *qkvf, *attf, *x2, *actf, *wf;
    cudaGetSymbolAddress((void**)&lnf,  g_ln);
    cudaGetSymbolAddress((void**)&qkvf, g_qkv);
    cudaGetSymbolAddress((void**)&attf, g_att);
    cudaGetSymbolAddress((void**)&x2,   g_x2);
    cudaGetSymbolAddress((void**)&actf, g_act);
    cudaGetSymbolAddress((void**)&wf,   g_w);
    __half* ln  = (__half*)lnf;
    __half* qkv = (__half*)qkvf;
    __half* att = (__half*)attf;
    __half* act = (__half*)actf;
    __half* w   = (__half*)wf;

    cudaFuncSetAttribute(mma_gemm<false, false, true>,
                         cudaFuncAttributeMaxDynamicSharedMemorySize, GSMEM_BYTES);
    cudaFuncSetAttribute(mma_gemm<false, true, false>,
                         cudaFuncAttributeMaxDynamicSharedMemorySize, GSMEM_BYTES);
    cudaFuncSetAttribute(mma_gemm<true, false, true>,
                         cudaFuncAttributeMaxDynamicSharedMemorySize, GSMEM_BYTES);
    cudaFuncSetAttribute(attn_mma_kernel,
                         cudaFuncAttributeMaxDynamicSharedMemorySize, ATT_SMEM);

    // 0. Convert all weights fp32 -> fp16 in one launch (natural layout)
    convert_all_kernel<<<4096, 256>>>((const float4*)c_attn_w, (const float4*)c_proj_w,
                                      (const float4*)mlp_w1, (const float4*)mlp_w2,
                                      (uint2*)w);

    // 1. LN1 (fp16 out)
    ln_kernel<<<MM/8, 256>>>(x, ln1_g, ln1_b, ln);
    // 2. QKV = ln @ c_attn_w + b           [4096, 3072] fp16 out
    mma_gemm<false, false, true><<<dim3(3*EE/256, MM/128), 256, GSMEM_BYTES>>>(
        ln, w + WH_ATTN, c_attn_b, nullptr, qkv, MM, 3*EE, EE);
    // 3. Attention (64-query CTAs, register-resident P, 3-stage KV)
    attn_mma_kernel<<<dim3(TT/64, HH, BB), 128, ATT_SMEM>>>(qkv, att);
    // 4. x2 = x + att @ c_proj_w + b       [4096, 1024] fp32 out
    mma_gemm<false, true, false><<<dim3(EE/256, MM/128), 256, GSMEM_BYTES>>>(
        att, w + WH_PROJ, c_proj_b, x, x2, MM, EE, EE);
    // 5. LN2 (fp16 out)
    ln_kernel<<<MM/8, 256>>>(x2, ln2_g, ln2_b, ln);
    // 6. act = gelu(h @ mlp_w1 + b1)       [4096, 4096] fp16 out
    mma_gemm<true, false, true><<<dim3(FF/256, MM/128), 256, GSMEM_BYTES>>>(
        ln, w + WH_MLP1, mlp_b1, nullptr, act, MM, FF, EE);
    // 7. out = x2 + act @ mlp_w2 + b2      [4096, 1024] fp32 out
    mma_gemm<false, true, false><<<dim3(EE/256, MM/128), 256, GSMEM_BYTES>>>(
        act, w + WH_MLP2, mlp_b2, x2, out, MM, EE, FF);
}

// round 17
// speedup vs baseline: 1.0175x; 1.0129x over previous
#include <cuda_runtime.h>
#include <cuda_fp16.h>
#include <math.h>
#include <stdint.h>

// Problem constants
#define BB 2
#define TT 2048
#define EE 1024
#define HH 16
#define DH 64
#define FF 4096
#define MM (BB*TT)   // 4096 rows

// Scratch (device globals: no allocation allowed)
__device__ float g_ln [MM*EE];         // as __half
__device__ float g_qkv[MM*3*EE];       // as __half
__device__ float g_att[MM*EE];         // as __half
__device__ float g_x2 [MM*EE];         // fp32
__device__ float g_act[(size_t)MM*FF]; // as __half
__device__ float g_w  [6*1024*1024];   // fp16 weights, NATURAL [K][N] layout

// offsets in halves
#define WH_ATTN 0
#define WH_PROJ (3*EE*EE)
#define WH_MLP1 (WH_PROJ + EE*EE)
#define WH_MLP2 (WH_MLP1 + EE*FF)

// ---------------------------------------------------------------------------
// Helpers
// ---------------------------------------------------------------------------
__device__ __forceinline__ void cp16(uint32_t dst, const void* src) {
    asm volatile("cp.async.cg.shared.global [%0], [%1], 16;\n" :: "r"(dst), "l"(src));
}

__device__ __forceinline__ uint32_t packh2(float a, float b) {
    __half2 h = __floats2half2_rn(a, b);
    return *reinterpret_cast<uint32_t*>(&h);
}

__device__ __forceinline__ uint32_t ex2h2(uint32_t x) {
    uint32_t r;
    asm("ex2.approx.f16x2 %0, %1;" : "=r"(r) : "r"(x));
    return r;
}

__device__ __forceinline__ float2 unpackh2(uint32_t x) {
    __half2 h = *reinterpret_cast<__half2*>(&x);
    return __half22float2(h);
}

#define MMA_F16(d0,d1,d2,d3,a0,a1,a2,a3,b0,b1) \
    asm volatile( \
        "mma.sync.aligned.m16n8k16.row.col.f32.f16.f16.f32 " \
        "{%0,%1,%2,%3}, {%4,%5,%6,%7}, {%8,%9}, {%0,%1,%2,%3};" \
        : "+f"(d0), "+f"(d1), "+f"(d2), "+f"(d3) \
        : "r"(a0), "r"(a1), "r"(a2), "r"(a3), "r"(b0), "r"(b1))

#define LDSM_X4(r0,r1,r2,r3,addr) \
    asm volatile("ldmatrix.sync.aligned.m8n8.x4.shared.b16 {%0,%1,%2,%3}, [%4];" \
        : "=r"(r0), "=r"(r1), "=r"(r2), "=r"(r3) : "r"(addr))

#define LDSM_X4_T(r0,r1,r2,r3,addr) \
    asm volatile("ldmatrix.sync.aligned.m8n8.x4.trans.shared.b16 {%0,%1,%2,%3}, [%4];" \
        : "=r"(r0), "=r"(r1), "=r"(r2), "=r"(r3) : "r"(addr))

// ---------------------------------------------------------------------------
// Fused fp32->fp16 convert for all four weights (dsts contiguous in g_w)
// ---------------------------------------------------------------------------
#define CV_S0 786432
#define CV_S1 1048576
#define CV_S2 2097152
#define CV_N  3145728
__global__ void convert_all_kernel(const float4* __restrict__ wa,
                                   const float4* __restrict__ wp,
                                   const float4* __restrict__ w1,
                                   const float4* __restrict__ w2,
                                   uint2* __restrict__ out) {
    int i = blockIdx.x * blockDim.x + threadIdx.x;
    int stride = gridDim.x * blockDim.x;
    for (; i < CV_N; i += stride) {
        float4 v;
        if (i < CV_S0)      v = wa[i];
        else if (i < CV_S1) v = wp[i - CV_S0];
        else if (i < CV_S2) v = w1[i - CV_S1];
        else                v = w2[i - CV_S2];
        uint2 o;
        o.x = packh2(v.x, v.y);
        o.y = packh2(v.z, v.w);
        out[i] = o;
    }
}

// ---------------------------------------------------------------------------
// LayerNorm: warp per row. 8 warps/block.
// ---------------------------------------------------------------------------
__global__ void ln_kernel(const float* __restrict__ x,
                          const float* __restrict__ g,
                          const float* __restrict__ b,
                          __half* __restrict__ out) {
    int row  = blockIdx.x * 8 + (threadIdx.x >> 5);
    int lane = threadIdx.x & 31;
    const float4* xr = reinterpret_cast<const float4*>(x + (size_t)row * EE);
    float4 v[8];
    float s = 0.f, sq = 0.f;
    #pragma unroll
    for (int i = 0; i < 8; i++) {
        v[i] = xr[i * 32 + lane];
        s  += v[i].x + v[i].y + v[i].z + v[i].w;
        sq += v[i].x*v[i].x + v[i].y*v[i].y + v[i].z*v[i].z + v[i].w*v[i].w;
    }
    #pragma unroll
    for (int o = 16; o > 0; o >>= 1) {
        s  += __shfl_xor_sync(0xffffffff, s,  o);
        sq += __shfl_xor_sync(0xffffffff, sq, o);
    }
    float mu   = s * (1.0f / EE);
    float rstd = rsqrtf(sq * (1.0f / EE) - mu * mu + 1e-5f);
    uint2* op = reinterpret_cast<uint2*>(out + (size_t)row * EE);
    const float4* gr = reinterpret_cast<const float4*>(g);
    const float4* br = reinterpret_cast<const float4*>(b);
    #pragma unroll
    for (int i = 0; i < 8; i++) {
        float4 gv = gr[i * 32 + lane];
        float4 bv = br[i * 32 + lane];
        uint2 o;
        o.x = packh2((v[i].x - mu) * rstd * gv.x + bv.x,
                     (v[i].y - mu) * rstd * gv.y + bv.y);
        o.y = packh2((v[i].z - mu) * rstd * gv.z + bv.z,
                     (v[i].w - mu) * rstd * gv.w + bv.w);
        op[i * 32 + lane] = o;
    }
}

__device__ __forceinline__ float gelu_f(float x) {
    const float c = 0.7978845608028654f;
    float x3 = x * x * x;
    return 0.5f * x * (1.0f + tanhf(c * (x + 0.044715f * x3)));
}

// ---------------------------------------------------------------------------
// fp16 GEMM, CTA 128x256x64, 8 warps (2x4), warp tile 64x64, fp32 accum.
// (frozen at measured HMMA-path rate)
// ---------------------------------------------------------------------------
#define GSTAGE 49152
#define GSMEM_BYTES (3*GSTAGE)

template<bool GELU, bool RES, bool OUTH>
__global__ void __launch_bounds__(256, 1)
mma_gemm(const __half* __restrict__ A, const __half* __restrict__ W,
         const float* __restrict__ bias, const float* __restrict__ res,
         void* __restrict__ Cv, int M, int N, int K) {
    extern __shared__ char smc[];
    const uint32_t sm_u = (uint32_t)__cvta_generic_to_shared(smc);

    const int tid  = threadIdx.x;
    const int lane = tid & 31;
    const int warp = tid >> 5;
    const int wm = warp >> 2;
    const int wn = warp & 3;
    const int g  = lane >> 2;
    const int tg = lane & 3;

    const int bm = blockIdx.y, bn = blockIdx.x;
    const __half* Ab = A + (size_t)bm * 128 * K;
    const __half* Bb = W + (size_t)bn * 256;

    const int j    = lane & 7;
    const int tile = lane >> 3;
    const uint32_t jm = (uint32_t)(j * 16);
    const uint32_t aRowSel = (uint32_t)((tile & 1) * 8);
    const uint32_t aC16    = (uint32_t)((tile >> 1) * 16);
    const uint32_t nbOff   = (uint32_t)((tile >> 1) * 16);

    uint32_t aRow[4];
    #pragma unroll
    for (int mi = 0; mi < 4; mi++)
        aRow[mi] = ((uint32_t)(wm * 64 + mi * 16 + j) + aRowSel) * 128;
    const uint32_t bBase = 16384u + (uint32_t)wn * 128u +
                           (uint32_t)(tile & 1) * 4096u + (uint32_t)j * 512u;

    float acc[4][8][4];
    #pragma unroll
    for (int i = 0; i < 4; i++)
        #pragma unroll
        for (int jj = 0; jj < 8; jj++)
            #pragma unroll
            for (int c = 0; c < 4; c++) acc[i][jj][c] = 0.f;

    auto issue = [&](int stage, int kt) {
        uint32_t sA = sm_u + (uint32_t)stage * GSTAGE;
        uint32_t sB = sA + 16384u;
        {
            int c = tid & 7;
            int kc = kt * 64 + c * 8;
            #pragma unroll
            for (int p = 0; p < 4; p++) {
                int r = (tid >> 3) + p * 32;
                uint32_t dst = (uint32_t)(r * 128) +
                               (((uint32_t)(c * 16)) ^ ((uint32_t)(r & 7) * 16));
                cp16(sA + dst, Ab + (size_t)r * K + kc);
            }
        }
        #pragma unroll
        for (int p = 0; p < 8; p++) {
            int idx = tid + p * 256;
            int r = idx >> 5;
            int c = idx & 31;
            uint32_t dst = (uint32_t)(r * 512) + (uint32_t)((c >> 3) * 128) +
                           (((uint32_t)((c & 7) * 16)) ^ ((uint32_t)(r & 7) * 16));
            cp16(sB + dst, Bb + (size_t)(kt * 64 + r) * N + c * 8);
        }
        asm volatile("cp.async.commit_group;\n");
    };

    const int KT = K >> 6;
    issue(0, 0);
    issue(1, 1);

    int rbuf = 0, ibuf = 2;
    for (int kt = 0; kt < KT; kt++) {
        if (kt + 1 < KT) {
            asm volatile("cp.async.wait_group 1;\n");
        } else {
            asm volatile("cp.async.wait_group 0;\n");
        }
        __syncthreads();
        if (kt + 2 < KT) {
            issue(ibuf, kt + 2);
            if (++ibuf == 3) ibuf = 0;
        }

        const uint32_t stBase = sm_u + (uint32_t)rbuf * GSTAGE;
        if (++rbuf == 3) rbuf = 0;

        #pragma unroll
        for (int ks = 0; ks < 4; ks++) {
            const uint32_t koffA = ((uint32_t)(ks * 32) + aC16) ^ jm;

            uint32_t af[4][4];
            #pragma unroll
            for (int mi = 0; mi < 4; mi++)
                LDSM_X4(af[mi][0], af[mi][1], af[mi][2], af[mi][3],
                        stBase + aRow[mi] + koffA);

            uint32_t bf[8][2];
            const uint32_t bk = stBase + bBase + (uint32_t)ks * 8192u;
            #pragma unroll
            for (int li = 0; li < 4; li++) {
                uint32_t addr = bk + (((uint32_t)(li * 32) + nbOff) ^ jm);
                LDSM_X4_T(bf[li*2][0], bf[li*2][1], bf[li*2+1][0], bf[li*2+1][1], addr);
            }

            #pragma unroll
            for (int mi = 0; mi < 4; mi++)
                #pragma unroll
                for (int ni = 0; ni < 8; ni++)
                    MMA_F16(acc[mi][ni][0], acc[mi][ni][1], acc[mi][ni][2], acc[mi][ni][3],
                            af[mi][0], af[mi][1], af[mi][2], af[mi][3],
                            bf[ni][0], bf[ni][1]);
        }
    }

    const int rowBase = bm * 128 + wm * 64;
    const int colBase = bn * 256 + wn * 64;
    float* Cf = (float*)Cv;
    __half* Ch = (__half*)Cv;
    float2 bb[8];
    #pragma unroll
    for (int ni = 0; ni < 8; ni++)
        bb[ni] = *reinterpret_cast<const float2*>(bias + colBase + ni * 8 + 2 * tg);
    #pragma unroll
    for (int mi = 0; mi < 4; mi++) {
        #pragma unroll
        for (int ni = 0; ni < 8; ni++) {
            int col = colBase + ni * 8 + 2 * tg;
            int r0 = rowBase + mi * 16 + g;
            int r1 = r0 + 8;
            float v0 = acc[mi][ni][0] + bb[ni].x;
            float v1 = acc[mi][ni][1] + bb[ni].y;
            float v2 = acc[mi][ni][2] + bb[ni].x;
            float v3 = acc[mi][ni][3] + bb[ni].y;
            if (GELU) { v0 = gelu_f(v0); v1 = gelu_f(v1); v2 = gelu_f(v2); v3 = gelu_f(v3); }
            if (RES) {
                const float2 rr0 = *reinterpret_cast<const float2*>(res + (size_t)r0 * N + col);
                const float2 rr1 = *reinterpret_cast<const float2*>(res + (size_t)r1 * N + col);
                v0 += rr0.x; v1 += rr0.y; v2 += rr1.x; v3 += rr1.y;
            }
            if (OUTH) {
                *reinterpret_cast<__half2*>(Ch + (size_t)r0 * N + col) = __floats2half2_rn(v0, v1);
                *reinterpret_cast<__half2*>(Ch + (size_t)r1 * N + col) = __floats2half2_rn(v2, v3);
            } else {
                *reinterpret_cast<float2*>(Cf + (size_t)r0 * N + col) = make_float2(v0, v1);
                *reinterpret_cast<float2*>(Cf + (size_t)r1 * N + col) = make_float2(v2, v3);
            }
        }
    }
}

// ---------------------------------------------------------------------------
// fp16 flash attention — R12 structure + f16x2 packed exponentials:
// softmax computes diffs in fp32, packs to half2, one ex2.approx.f16x2 per
// pair (halving MUFU ops); results ARE the P fragments for P@V.
// 64-query CTAs, 4 warps, 3-stage KV ring, 3 CTAs/SM.
// ---------------------------------------------------------------------------
#define AOFF_V 24576u
#define AOFF_Q 49152u
#define ATT_SMEM 57344

__global__ void __launch_bounds__(128, 3)
attn_mma_kernel(const __half* __restrict__ qkv, __half* __restrict__ out) {
    extern __shared__ char smc[];
    const uint32_t sm_u = (uint32_t)__cvta_generic_to_shared(smc);

    const int qt  = gridDim.x - 1 - blockIdx.x;
    const int qt0 = qt * 64;
    const int h   = blockIdx.y;
    const int b   = blockIdx.z;
    const int tid = threadIdx.x;
    const int lane = tid & 31;
    const int warp = tid >> 5;
    const int g  = lane >> 2;
    const int tg = lane & 3;
    const int r0 = warp * 16 + g;

    const int j    = lane & 7;
    const int tile = lane >> 3;
    const uint32_t jm = (uint32_t)(j * 16);
    const uint32_t aRowSel = (uint32_t)((tile & 1) * 8);
    const uint32_t aC16    = (uint32_t)((tile >> 1) * 16);
    const uint32_t bRowSel = (uint32_t)((tile >> 1) * 8);
    const uint32_t bC16    = (uint32_t)((tile & 1) * 16);

    const __half* base = qkv + (size_t)b * TT * (3 * EE);
    const int sch = (tid & 7) << 4;

    auto issueKV = [&](int stage, int kt) {
        int krow0 = kt * 64;
        uint32_t sK = sm_u + (uint32_t)stage * 8192u;
        uint32_t sV = sm_u + AOFF_V + (uint32_t)stage * 8192u;
        #pragma unroll
        for (int p = 0; p < 4; p++) {
            int r = (tid >> 3) + p * 16;
            uint32_t dst = (uint32_t)(r * 128) + ((uint32_t)sch ^ ((uint32_t)(r & 7) * 16));
            const __half* src = base + (size_t)(krow0 + r) * 3072 + EE + h * 64 + (sch >> 1);
            cp16(sK + dst, src);
            cp16(sV + dst, src + EE);
        }
        asm volatile("cp.async.commit_group;\n");
    };

    const int nkt = qt + 1;
    issueKV(0, 0);
    if (nkt > 1) issueKV(1, 1);

    {
        // Q pre-scale: 1/8 * log2(e) -> softmax in base-2 domain
        const __half2 sc8 = __float2half2_rn(0.18033688f);
        #pragma unroll
        for (int p = 0; p < 4; p++) {
            int r = (tid >> 3) + p * 16;
            uint4 q = *reinterpret_cast<const uint4*>(
                base + (size_t)(qt0 + r) * 3072 + h * 64 + (sch >> 1));
            __half2* qh = reinterpret_cast<__half2*>(&q);
            qh[0] = __hmul2(qh[0], sc8);
            qh[1] = __hmul2(qh[1], sc8);
            qh[2] = __hmul2(qh[2], sc8);
            qh[3] = __hmul2(qh[3], sc8);
            uint32_t dst = AOFF_Q + (uint32_t)(r * 128) +
                           ((uint32_t)sch ^ ((uint32_t)(r & 7) * 16));
            *reinterpret_cast<uint4*>(smc + dst) = q;
        }
    }
    __syncthreads();

    uint32_t qa[4][4];
    #pragma unroll
    for (int ks = 0; ks < 4; ks++) {
        uint32_t addr = sm_u + AOFF_Q +
            ((uint32_t)(warp * 16 + j) + aRowSel) * 128 +
            (((uint32_t)(ks * 32) + aC16) ^ jm);
        LDSM_X4(qa[ks][0], qa[ks][1], qa[ks][2], qa[ks][3], addr);
    }

    float m0 = -1e30f, m1 = -1e30f, l0 = 0.f, l1 = 0.f;
    float ob[8][4];
    #pragma unroll
    for (int nt = 0; nt < 8; nt++)
        #pragma unroll
        for (int c = 0; c < 4; c++) ob[nt][c] = 0.f;

    int rstage = 0, istage = 2;
    for (int kt = 0; kt < nkt; kt++) {
        if (kt + 1 < nkt) {
            asm volatile("cp.async.wait_group 1;\n");
        } else {
            asm volatile("cp.async.wait_group 0;\n");
        }
        __syncthreads();
        if (kt + 2 < nkt) {
            issueKV(istage, kt + 2);
            if (++istage == 3) istage = 0;
        }

        const uint32_t sK = sm_u + (uint32_t)rstage * 8192u;
        const uint32_t sV = sm_u + AOFF_V + (uint32_t)rstage * 8192u;
        if (++rstage == 3) rstage = 0;

        // S = Q @ K^T
        float sc[8][4];
        #pragma unroll
        for (int nt = 0; nt < 8; nt++)
            #pragma unroll
            for (int c = 0; c < 4; c++) sc[nt][c] = 0.f;

        #pragma unroll
        for (int ks = 0; ks < 4; ks++) {
            const uint32_t koffB = ((uint32_t)(ks * 32) + bC16) ^ jm;
            uint32_t bfr[8][2];
            #pragma unroll
            for (int bi = 0; bi < 4; bi++) {
                uint32_t addr = sK + ((uint32_t)(bi * 16 + j) + bRowSel) * 128 + koffB;
                LDSM_X4(bfr[bi*2][0], bfr[bi*2][1], bfr[bi*2+1][0], bfr[bi*2+1][1], addr);
            }
            #pragma unroll
            for (int nt = 0; nt < 8; nt++)
                MMA_F16(sc[nt][0], sc[nt][1], sc[nt][2], sc[nt][3],
                        qa[ks][0], qa[ks][1], qa[ks][2], qa[ks][3],
                        bfr[nt][0], bfr[nt][1]);
        }

        // Causal mask (diagonal tile)
        if (kt == nkt - 1) {
            int qrow0 = qt0 + r0;
            int qrow1 = qrow0 + 8;
            #pragma unroll
            for (int nt = 0; nt < 8; nt++) {
                int kc0 = kt * 64 + nt * 8 + 2 * tg;
                if (kc0     > qrow0) sc[nt][0] = -1e30f;
                if (kc0 + 1 > qrow0) sc[nt][1] = -1e30f;
                if (kc0     > qrow1) sc[nt][2] = -1e30f;
                if (kc0 + 1 > qrow1) sc[nt][3] = -1e30f;
            }
        }

        // Online softmax (base-2). Row max:
        float rm0 = -1e30f, rm1 = -1e30f;
        #pragma unroll
        for (int nt = 0; nt < 8; nt++) {
            rm0 = fmaxf(rm0, fmaxf(sc[nt][0], sc[nt][1]));
            rm1 = fmaxf(rm1, fmaxf(sc[nt][2], sc[nt][3]));
        }
        rm0 = fmaxf(rm0, __shfl_xor_sync(0xffffffff, rm0, 1));
        rm0 = fmaxf(rm0, __shfl_xor_sync(0xffffffff, rm0, 2));
        rm1 = fmaxf(rm1, __shfl_xor_sync(0xffffffff, rm1, 1));
        rm1 = fmaxf(rm1, __shfl_xor_sync(0xffffffff, rm1, 2));
        float mn0 = fmaxf(m0, rm0);
        float mn1 = fmaxf(m1, rm1);

        // Packed fp16 exponentials: pe[nt][0] = exp2(sc[nt][0..1]-mn0) as h2
        // (rows r0), pe[nt][1] = exp2(sc[nt][2..3]-mn1) (rows r0+8). These
        // ARE the P A-fragments. Masked entries: -1e30-mn -> f16 -Inf -> 0.
        uint32_t pe[8][2];
        float rs0 = 0.f, rs1 = 0.f;
        #pragma unroll
        for (int nt = 0; nt < 8; nt++) {
            pe[nt][0] = ex2h2(packh2(sc[nt][0] - mn0, sc[nt][1] - mn0));
            pe[nt][1] = ex2h2(packh2(sc[nt][2] - mn1, sc[nt][3] - mn1));
            float2 f0 = unpackh2(pe[nt][0]);
            float2 f1 = unpackh2(pe[nt][1]);
            rs0 += f0.x + f0.y;
            rs1 += f1.x + f1.y;
        }
        rs0 += __shfl_xor_sync(0xffffffff, rs0, 1);
        rs0 += __shfl_xor_sync(0xffffffff, rs0, 2);
        rs1 += __shfl_xor_sync(0xffffffff, rs1, 1);
        rs1 += __shfl_xor_sync(0xffffffff, rs1, 2);

        float scale0 = exp2f(m0 - mn0);
        float scale1 = exp2f(m1 - mn1);
        l0 = l0 * scale0 + rs0;
        l1 = l1 * scale1 + rs1;
        m0 = mn0; m1 = mn1;
        #pragma unroll
        for (int nt = 0; nt < 8; nt++) {
            ob[nt][0] *= scale0; ob[nt][1] *= scale0;
            ob[nt][2] *= scale1; ob[nt][3] *= scale1;
        }

        // O += P @ V — fragments straight from pe
        #pragma unroll
        for (int ks = 0; ks < 4; ks++) {
            uint32_t vf[8][2];
            #pragma unroll
            for (int li = 0; li < 4; li++) {
                uint32_t addr = sV +
                    (uint32_t)((ks * 16 + (tile & 1) * 8 + j) * 128) +
                    (((uint32_t)(li * 32 + (tile >> 1) * 16)) ^ jm);
                LDSM_X4_T(vf[li*2][0], vf[li*2][1], vf[li*2+1][0], vf[li*2+1][1], addr);
            }
            #pragma unroll
            for (int nt = 0; nt < 8; nt++)
                MMA_F16(ob[nt][0], ob[nt][1], ob[nt][2], ob[nt][3],
                        pe[2*ks][0], pe[2*ks][1], pe[2*ks+1][0], pe[2*ks+1][1],
                        vf[nt][0], vf[nt][1]);
        }
    }

    float inv0 = 1.0f / l0;
    float inv1 = 1.0f / l1;
    size_t row0 = ((size_t)b * TT + qt0 + r0) * EE + h * 64;
    size_t row1 = row0 + 8 * EE;
    #pragma unroll
    for (int nt = 0; nt < 8; nt++) {
        int col = nt * 8 + 2 * tg;
        *reinterpret_cast<__half2*>(out + row0 + col) =
            __floats2half2_rn(ob[nt][0] * inv0, ob[nt][1] * inv0);
        *reinterpret_cast<__half2*>(out + row1 + col) =
            __floats2half2_rn(ob[nt][2] * inv1, ob[nt][3] * inv1);
    }
}

// ---------------------------------------------------------------------------
// Launch
// ---------------------------------------------------------------------------
extern "C" void kernel_launch(void* const* d_in, const int* in_sizes, int n_in,
                              void* d_out, int out_size) {
    const float* x        = (const float*)d_in[0];
    const float* c_attn_w = (const float*)d_in[1];
    const float* c_attn_b = (const float*)d_in[2];
    const float* c_proj_w = (const float*)d_in[3];
    const float* c_proj_b = (const float*)d_in[4];
    const float* mlp_w1   = (const float*)d_in[5];
    const float* mlp_b1   = (const float*)d_in[6];
    const float* mlp_w2   = (const float*)d_in[7];
    const float* mlp_b2   = (const float*)d_in[8];
    const float* ln1_g    = (const float*)d_in[9];
    const float* ln1_b    = (const float*)d_in[10];
    const float* ln2_g    = (const float*)d_in[11];
    const float* ln2_b    = (const float*)d_in[12];
    float* out = (float*)d_out;

    float *lnf, *qkvf, *attf, *x2, *actf, *wf;
    cudaGetSymbolAddress((void**)&lnf,  g_ln);
    cudaGetSymbolAddress((void**)&qkvf, g_qkv);
    cudaGetSymbolAddress((void**)&attf, g_att);
    cudaGetSymbolAddress((void**)&x2,   g_x2);
    cudaGetSymbolAddress((void**)&actf, g_act);
    cudaGetSymbolAddress((void**)&wf,   g_w);
    __half* ln  = (__half*)lnf;
    __half* qkv = (__half*)qkvf;
    __half* att = (__half*)attf;
    __half* act = (__half*)actf;
    __half* w   = (__half*)wf;

    cudaFuncSetAttribute(mma_gemm<false, false, true>,
                         cudaFuncAttributeMaxDynamicSharedMemorySize, GSMEM_BYTES);
    cudaFuncSetAttribute(mma_gemm<false, true, false>,
                         cudaFuncAttributeMaxDynamicSharedMemorySize, GSMEM_BYTES);
    cudaFuncSetAttribute(mma_gemm<true, false, true>,
                         cudaFuncAttributeMaxDynamicSharedMemorySize, GSMEM_BYTES);
    cudaFuncSetAttribute(attn_mma_kernel,
                         cudaFuncAttributeMaxDynamicSharedMemorySize, ATT_SMEM);

    // 0. Convert all weights fp32 -> fp16 in one launch (natural layout)
    convert_all_kernel<<<4096, 256>>>((const float4*)c_attn_w, (const float4*)c_proj_w,
                                      (const float4*)mlp_w1, (const float4*)mlp_w2,
                                      (uint2*)w);

    // 1. LN1 (fp16 out)
    ln_kernel<<<MM/8, 256>>>(x, ln1_g, ln1_b, ln);
    // 2. QKV = ln @ c_attn_w + b           [4096, 3072] fp16 out
    mma_gemm<false, false, true><<<dim3(3*EE/256, MM/128), 256, GSMEM_BYTES>>>(
        ln, w + WH_ATTN, c_attn_b, nullptr, qkv, MM, 3*EE, EE);
    // 3. Attention (64-query CTAs, f16x2 exponentials, register-resident P)
    attn_mma_kernel<<<dim3(TT/64, HH, BB), 128, ATT_SMEM>>>(qkv, att);
    // 4. x2 = x + att @ c_proj_w + b       [4096, 1024] fp32 out
    mma_gemm<false, true, false><<<dim3(EE/256, MM/128), 256, GSMEM_BYTES>>>(
        att, w + WH_PROJ, c_proj_b, x, x2, MM, EE, EE);
    // 5. LN2 (fp16 out)
    ln_kernel<<<MM/8, 256>>>(x2, ln2_g, ln2_b, ln);
    // 6. act = gelu(h @ mlp_w1 + b1)       [4096, 4096] fp16 out
    mma_gemm<true, false, true><<<dim3(FF/256, MM/128), 256, GSMEM_BYTES>>>(
        ln, w + WH_MLP1, mlp_b1, nullptr, act, MM, FF, EE);
    // 7. out = x2 + act @ mlp_w2 + b2      [4096, 1024] fp32 out
    mma_gemm<false, true, false><<<dim3(EE/256, MM/128), 256, GSMEM_BYTES>>>(
        act, w + WH_MLP2, mlp_b2, x2, out, MM, EE, FF);
}